// round 1
// baseline (speedup 1.0000x reference)
#include <cuda_runtime.h>
#include <math.h>

#define NUM_USERS 100000
#define NUM_ITEMS 50000
#define N_NODES   150000
#define N_EDGES   2400000
#define EMB       64
#define BATCH     4096
#define LAYERS    3
#define TAU       0.2f
#define SSL_LAMBDA 0.1f
#define REG_LAMBDA 1e-4f

#define NVEC4 (N_NODES * EMB / 4)   // 2,400,000 float4s in a table

// ---------------- device scratch (static, no runtime allocation) -------------
__device__ __align__(16) float g_e0[N_NODES * EMB];
__device__ __align__(16) float g_e1[N_NODES * EMB];
__device__ __align__(16) float g_acc[N_NODES * EMB];
__device__ __align__(16) float g_un[BATCH * EMB];
__device__ __align__(16) float g_pn[BATCH * EMB];
__device__ __align__(16) float g_logits[(size_t)BATCH * BATCH];
__device__ float g_scal[4];   // [0]=bpr softplus sum, [1]=reg sum, [2]=na sum

// ---------------- init: e0 = concat(user_emb, item_emb); acc = e0 ------------
__global__ __launch_bounds__(256) void k_init(const float* __restrict__ uw,
                                              const float* __restrict__ iw) {
    int i = blockIdx.x * blockDim.x + threadIdx.x;
    if (i < 4) g_scal[i] = 0.0f;
    if (i >= NVEC4) return;
    const int UV = NUM_USERS * EMB / 4;
    float4 v = (i < UV) ? ((const float4*)uw)[i] : ((const float4*)iw)[i - UV];
    ((float4*)g_e0)[i]  = v;
    ((float4*)g_acc)[i] = v;
}

// ---------------- zero a table -----------------------------------------------
__global__ __launch_bounds__(256) void k_zero(float* __restrict__ p) {
    int i = blockIdx.x * blockDim.x + threadIdx.x;
    if (i >= NVEC4) return;
    ((float4*)p)[i] = make_float4(0.f, 0.f, 0.f, 0.f);
}

// ---------------- edge scatter: e_out[row] += val * e_in[col] ----------------
// thread = (edge, 16B chunk). 16 consecutive threads share one edge, so the
// gather of the 256B source row is perfectly coalesced and edge metadata loads
// are warp-broadcast. Scatter uses vectorized red.global.add.v4.f32.
__global__ __launch_bounds__(256) void k_edges(const int*   __restrict__ rows,
                                               const int*   __restrict__ cols,
                                               const float* __restrict__ vals,
                                               const float* __restrict__ e_in,
                                               float*       __restrict__ e_out) {
    unsigned idx = blockIdx.x * blockDim.x + threadIdx.x;
    if (idx >= (unsigned)N_EDGES * 16u) return;
    int e = idx >> 4;
    int c = (idx & 15) << 2;                    // float offset within row
    int r  = rows[e];
    int cl = cols[e];
    float v = vals[e];
    float4 s = *(const float4*)(e_in + (size_t)cl * EMB + c);
    float* dst = e_out + (size_t)r * EMB + c;
    asm volatile("red.global.add.v4.f32 [%0], {%1, %2, %3, %4};"
                 :: "l"(dst), "f"(s.x * v), "f"(s.y * v), "f"(s.z * v), "f"(s.w * v)
                 : "memory");
}

// ---------------- acc += e ---------------------------------------------------
__global__ __launch_bounds__(256) void k_accum(const float* __restrict__ e) {
    int i = blockIdx.x * blockDim.x + threadIdx.x;
    if (i >= NVEC4) return;
    float4 a = ((float4*)g_acc)[i];
    float4 b = ((const float4*)e)[i];
    a.x += b.x; a.y += b.y; a.z += b.z; a.w += b.w;
    ((float4*)g_acc)[i] = a;
}

// ---------------- gather batch rows, BPR + reg partials, normalize ----------
// one warp per batch element; each lane owns 2 of the 64 dims.
__global__ __launch_bounds__(256) void k_gather(const int* __restrict__ user,
                                                const int* __restrict__ pos,
                                                const int* __restrict__ neg) {
    int gw   = (blockIdx.x * blockDim.x + threadIdx.x) >> 5;
    int lane = threadIdx.x & 31;
    if (gw >= BATCH) return;
    size_t uoff = (size_t)user[gw] * EMB;
    size_t poff = (size_t)(NUM_USERS + pos[gw]) * EMB;
    size_t noff = (size_t)(NUM_USERS + neg[gw]) * EMB;
    float2 u = *(const float2*)(g_acc + uoff + lane * 2);
    float2 p = *(const float2*)(g_acc + poff + lane * 2);
    float2 n = *(const float2*)(g_acc + noff + lane * 2);
    const float inv = 1.0f / (LAYERS + 1);
    u.x *= inv; u.y *= inv; p.x *= inv; p.y *= inv; n.x *= inv; n.y *= inv;

    float s_up = u.x * p.x + u.y * p.y;
    float s_un = u.x * n.x + u.y * n.y;
    float s_uu = u.x * u.x + u.y * u.y;
    float s_pp = p.x * p.x + p.y * p.y;
    float s_nn = n.x * n.x + n.y * n.y;
    #pragma unroll
    for (int o = 16; o; o >>= 1) {
        s_up += __shfl_xor_sync(0xffffffffu, s_up, o);
        s_un += __shfl_xor_sync(0xffffffffu, s_un, o);
        s_uu += __shfl_xor_sync(0xffffffffu, s_uu, o);
        s_pp += __shfl_xor_sync(0xffffffffu, s_pp, o);
        s_nn += __shfl_xor_sync(0xffffffffu, s_nn, o);
    }
    float iu = rsqrtf(s_uu);
    float ip = rsqrtf(s_pp);
    *(float2*)(g_un + (size_t)gw * EMB + lane * 2) = make_float2(u.x * iu, u.y * iu);
    *(float2*)(g_pn + (size_t)gw * EMB + lane * 2) = make_float2(p.x * ip, p.y * ip);
    if (lane == 0) {
        float d  = s_up - s_un;
        float sp = fmaxf(-d, 0.0f) + log1pf(expf(-fabsf(d)));  // softplus(-d)
        atomicAdd(&g_scal[0], sp);
        atomicAdd(&g_scal[1], s_uu + s_pp + s_nn);
    }
}

// ---------------- logits = (un @ pn^T) / tau : 64x64 tiles, K=64 -------------
__global__ __launch_bounds__(256) void k_gemm() {
    __shared__ float As[64][64];   // k-major: As[k][i]
    __shared__ float Bs[64][64];   // k-major: Bs[k][j]
    int bi = blockIdx.y * 64, bj = blockIdx.x * 64;
    int tid = threadIdx.x;
    #pragma unroll
    for (int t = 0; t < 4; t++) {
        int vi = tid + t * 256;          // 0..1023
        int r  = vi >> 4;                // row within tile
        int c  = (vi & 15) << 2;         // k offset
        float4 a = *(const float4*)(g_un + (size_t)(bi + r) * EMB + c);
        As[c + 0][r] = a.x; As[c + 1][r] = a.y; As[c + 2][r] = a.z; As[c + 3][r] = a.w;
        float4 b = *(const float4*)(g_pn + (size_t)(bj + r) * EMB + c);
        Bs[c + 0][r] = b.x; Bs[c + 1][r] = b.y; Bs[c + 2][r] = b.z; Bs[c + 3][r] = b.w;
    }
    __syncthreads();
    int ty = tid >> 4, tx = tid & 15;
    float acc[4][4];
    #pragma unroll
    for (int a = 0; a < 4; a++)
        #pragma unroll
        for (int b = 0; b < 4; b++) acc[a][b] = 0.0f;
    #pragma unroll 8
    for (int k = 0; k < 64; k++) {
        float4 av = *(const float4*)&As[k][ty * 4];
        float4 bv = *(const float4*)&Bs[k][tx * 4];
        float a4[4] = {av.x, av.y, av.z, av.w};
        float b4[4] = {bv.x, bv.y, bv.z, bv.w};
        #pragma unroll
        for (int a = 0; a < 4; a++)
            #pragma unroll
            for (int b = 0; b < 4; b++) acc[a][b] += a4[a] * b4[b];
    }
    const float invTau = 1.0f / TAU;
    #pragma unroll
    for (int a = 0; a < 4; a++) {
        size_t rowoff = (size_t)(bi + ty * 4 + a) * BATCH + bj + tx * 4;
        float4 o = make_float4(acc[a][0] * invTau, acc[a][1] * invTau,
                               acc[a][2] * invTau, acc[a][3] * invTau);
        *(float4*)(g_logits + rowoff) = o;
    }
}

// ---------------- per-row logsumexp - diagonal; sum into g_scal[2] -----------
__global__ __launch_bounds__(256) void k_lse() {
    int row = blockIdx.x;
    const float* L = g_logits + (size_t)row * BATCH;
    float m = -1e30f, s = 0.0f;
    for (int j = threadIdx.x; j < BATCH; j += 256) {
        float x = L[j];
        if (x > m) { s = s * __expf(m - x) + 1.0f; m = x; }
        else       { s += __expf(x - m); }
    }
    __shared__ float sm[256], ss[256];
    sm[threadIdx.x] = m; ss[threadIdx.x] = s;
    __syncthreads();
    for (int o = 128; o; o >>= 1) {
        if (threadIdx.x < o) {
            float m2 = sm[threadIdx.x + o], s2 = ss[threadIdx.x + o];
            float m1 = sm[threadIdx.x],     s1 = ss[threadIdx.x];
            float M = fmaxf(m1, m2);
            ss[threadIdx.x] = s1 * __expf(m1 - M) + s2 * __expf(m2 - M);
            sm[threadIdx.x] = M;
        }
        __syncthreads();
    }
    if (threadIdx.x == 0) {
        float lse = sm[0] + logf(ss[0]);
        atomicAdd(&g_scal[2], lse - L[row]);
    }
}

// ---------------- finalize ---------------------------------------------------
__global__ void k_final(float* out) {
    float bpr = g_scal[0] / BATCH;
    float reg = 0.5f * g_scal[1] / BATCH * REG_LAMBDA;
    float na  = g_scal[2] / BATCH * SSL_LAMBDA;
    out[0] = bpr + reg + na;
}

// ---------------- host ------------------------------------------------------
extern "C" void kernel_launch(void* const* d_in, const int* in_sizes, int n_in,
                              void* d_out, int out_size) {
    const int*   user  = (const int*)d_in[0];
    const int*   pos   = (const int*)d_in[1];
    const int*   neg   = (const int*)d_in[2];
    const int*   arow  = (const int*)d_in[3];
    const int*   acol  = (const int*)d_in[4];
    const float* aval  = (const float*)d_in[5];
    const float* uw    = (const float*)d_in[6];
    const float* iw    = (const float*)d_in[7];
    float* out = (float*)d_out;

    float *e0, *e1;
    cudaGetSymbolAddress((void**)&e0, g_e0);
    cudaGetSymbolAddress((void**)&e1, g_e1);
    float* buf[2] = {e0, e1};

    const int TB = 256;
    const int tab_blocks  = NVEC4 / TB;                       // 9375
    const int edge_blocks = (N_EDGES * 16) / TB;              // 150000

    k_init<<<tab_blocks, TB>>>(uw, iw);
    for (int l = 0; l < LAYERS; l++) {
        float* cur = buf[l & 1];
        float* nxt = buf[(l + 1) & 1];
        k_zero<<<tab_blocks, TB>>>(nxt);
        k_edges<<<edge_blocks, TB>>>(arow, acol, aval, cur, nxt);
        k_accum<<<tab_blocks, TB>>>(nxt);
    }
    k_gather<<<(BATCH * 32) / TB, TB>>>(user, pos, neg);
    k_gemm<<<dim3(BATCH / 64, BATCH / 64), TB>>>();
    k_lse<<<BATCH, TB>>>();
    k_final<<<1, 1>>>(out);
}

// round 2
// speedup vs baseline: 1.4032x; 1.4032x over previous
#include <cuda_runtime.h>
#include <math.h>

#define NUM_USERS 100000
#define NUM_ITEMS 50000
#define N_NODES   150000
#define N_EDGES   2400000
#define EMB       64
#define BATCH     4096
#define LAYERS    3
#define TAU       0.2f
#define SSL_LAMBDA 0.1f
#define REG_LAMBDA 1e-4f

#define NVEC4      (N_NODES * EMB / 4)    // 2,400,000 float4 per table
#define NROWS_PAD  150016                 // 586 * 256
#define SCAN_BLKS  586

// ---------------- device scratch (static, no runtime allocation) -------------
__device__ __align__(16) float g_e0[N_NODES * EMB];
__device__ __align__(16) float g_e1[N_NODES * EMB];
__device__ __align__(16) float g_e2[N_NODES * EMB];
__device__ __align__(16) float g_e3[N_NODES * EMB];
__device__ __align__(16) float g_un[BATCH * EMB];
__device__ __align__(16) float g_pn[BATCH * EMB];
__device__ __align__(16) float g_logits[(size_t)BATCH * BATCH];
__device__ float g_scal[4];

// CSR build scratch
__device__ int   g_deg[NROWS_PAD];
__device__ int   g_scan[NROWS_PAD];
__device__ int   g_blksum[1024];
__device__ int   g_blkoff[1024];
__device__ int   g_rowptr[NROWS_PAD];
__device__ int   g_fill[NROWS_PAD];
__device__ int   g_ccol[N_EDGES];
__device__ float g_cval[N_EDGES];

// ---------------- init: e0 = concat(user_emb, item_emb); zero counters -------
__global__ __launch_bounds__(256) void k_init(const float* __restrict__ uw,
                                              const float* __restrict__ iw) {
    int i = blockIdx.x * blockDim.x + threadIdx.x;
    if (i < 4) g_scal[i] = 0.0f;
    if (i < NROWS_PAD) g_deg[i] = 0;
    if (i >= NVEC4) return;
    const int UV = NUM_USERS * EMB / 4;
    float4 v = (i < UV) ? ((const float4*)uw)[i] : ((const float4*)iw)[i - UV];
    ((float4*)g_e0)[i] = v;
}

// ---------------- CSR build ---------------------------------------------------
__global__ __launch_bounds__(256) void k_hist(const int* __restrict__ rows) {
    int e = blockIdx.x * blockDim.x + threadIdx.x;
    if (e < N_EDGES) atomicAdd(&g_deg[rows[e]], 1);
}

__global__ __launch_bounds__(256) void k_scan_block() {
    int b = blockIdx.x, i = b * 256 + threadIdx.x;
    int v = g_deg[i];
    int lane = threadIdx.x & 31, wid = threadIdx.x >> 5;
    int x = v;
    #pragma unroll
    for (int o = 1; o < 32; o <<= 1) {
        int y = __shfl_up_sync(0xffffffffu, x, o);
        if (lane >= o) x += y;
    }
    __shared__ int wsum[8];
    if (lane == 31) wsum[wid] = x;
    __syncthreads();
    if (threadIdx.x < 8) {
        int t = wsum[threadIdx.x];
        #pragma unroll
        for (int o = 1; o < 8; o <<= 1) {
            int y = __shfl_up_sync(0xffu, t, o);
            if (threadIdx.x >= o) t += y;
        }
        wsum[threadIdx.x] = t;
    }
    __syncthreads();
    int base = wid ? wsum[wid - 1] : 0;
    int incl = x + base;
    g_scan[i] = incl - v;                    // block-local exclusive
    if (threadIdx.x == 255) g_blksum[b] = incl;
}

__global__ __launch_bounds__(1024) void k_scan_top() {
    __shared__ int sh[1024];
    int tid = threadIdx.x;
    int v = (tid < SCAN_BLKS) ? g_blksum[tid] : 0;
    sh[tid] = v;
    __syncthreads();
    for (int o = 1; o < 1024; o <<= 1) {
        int t = (tid >= o) ? sh[tid - o] : 0;
        __syncthreads();
        sh[tid] += t;
        __syncthreads();
    }
    if (tid < SCAN_BLKS) g_blkoff[tid] = sh[tid] - v;   // exclusive
}

__global__ __launch_bounds__(256) void k_scan_add() {
    int i = blockIdx.x * blockDim.x + threadIdx.x;
    if (i >= NROWS_PAD) return;
    int start = g_scan[i] + g_blkoff[i >> 8];
    g_rowptr[i] = start;
    g_fill[i]   = start;
}

__global__ __launch_bounds__(256) void k_scatter(const int*   __restrict__ rows,
                                                 const int*   __restrict__ cols,
                                                 const float* __restrict__ vals) {
    int e = blockIdx.x * blockDim.x + threadIdx.x;
    if (e >= N_EDGES) return;
    int r = rows[e];
    int p = atomicAdd(&g_fill[r], 1);
    g_ccol[p] = cols[e];
    g_cval[p] = vals[e];
}

// ---------------- CSR SpMM: e_out[r] = sum_j val_j * e_in[col_j] -------------
// one warp per row, 2 floats per lane, 4-way unrolled neighbor loop for MLP.
__global__ __launch_bounds__(256) void k_spmm(const float* __restrict__ e_in,
                                              float*       __restrict__ e_out) {
    int w = (blockIdx.x * 256 + threadIdx.x) >> 5;
    int lane = threadIdx.x & 31;
    if (w >= N_NODES) return;
    int start = g_rowptr[w];
    int deg   = g_deg[w];
    const int*   cc = g_ccol + start;
    const float* vv = g_cval + start;
    float ax = 0.f, ay = 0.f, bx = 0.f, by = 0.f;
    float cx = 0.f, cy = 0.f, dx = 0.f, dy = 0.f;
    int j = 0;
    for (; j + 4 <= deg; j += 4) {
        int   c0 = cc[j],   c1 = cc[j+1], c2 = cc[j+2], c3 = cc[j+3];
        float v0 = vv[j],   v1 = vv[j+1], v2 = vv[j+2], v3 = vv[j+3];
        float2 x0 = *(const float2*)(e_in + (size_t)c0 * EMB + lane * 2);
        float2 x1 = *(const float2*)(e_in + (size_t)c1 * EMB + lane * 2);
        float2 x2 = *(const float2*)(e_in + (size_t)c2 * EMB + lane * 2);
        float2 x3 = *(const float2*)(e_in + (size_t)c3 * EMB + lane * 2);
        ax += v0 * x0.x; ay += v0 * x0.y;
        bx += v1 * x1.x; by += v1 * x1.y;
        cx += v2 * x2.x; cy += v2 * x2.y;
        dx += v3 * x3.x; dy += v3 * x3.y;
    }
    for (; j < deg; j++) {
        int c = cc[j]; float v = vv[j];
        float2 x = *(const float2*)(e_in + (size_t)c * EMB + lane * 2);
        ax += v * x.x; ay += v * x.y;
    }
    float2 r;
    r.x = (ax + bx) + (cx + dx);
    r.y = (ay + by) + (cy + dy);
    *(float2*)(e_out + (size_t)w * EMB + lane * 2) = r;
}

// ---------------- gather batch rows, BPR + reg partials, normalize ------------
__global__ __launch_bounds__(256) void k_gather(const int* __restrict__ user,
                                                const int* __restrict__ pos,
                                                const int* __restrict__ neg) {
    int gw   = (blockIdx.x * blockDim.x + threadIdx.x) >> 5;
    int lane = threadIdx.x & 31;
    if (gw >= BATCH) return;
    size_t uoff = (size_t)user[gw] * EMB + lane * 2;
    size_t poff = (size_t)(NUM_USERS + pos[gw]) * EMB + lane * 2;
    size_t noff = (size_t)(NUM_USERS + neg[gw]) * EMB + lane * 2;
    const float inv = 0.25f;
    #define SUM4(off) make_float2( \
        (*(const float2*)(g_e0 + (off))).x + (*(const float2*)(g_e1 + (off))).x + \
        (*(const float2*)(g_e2 + (off))).x + (*(const float2*)(g_e3 + (off))).x, \
        (*(const float2*)(g_e0 + (off))).y + (*(const float2*)(g_e1 + (off))).y + \
        (*(const float2*)(g_e2 + (off))).y + (*(const float2*)(g_e3 + (off))).y)
    float2 u = SUM4(uoff); float2 p = SUM4(poff); float2 n = SUM4(noff);
    #undef SUM4
    u.x *= inv; u.y *= inv; p.x *= inv; p.y *= inv; n.x *= inv; n.y *= inv;

    float s_up = u.x * p.x + u.y * p.y;
    float s_un = u.x * n.x + u.y * n.y;
    float s_uu = u.x * u.x + u.y * u.y;
    float s_pp = p.x * p.x + p.y * p.y;
    float s_nn = n.x * n.x + n.y * n.y;
    #pragma unroll
    for (int o = 16; o; o >>= 1) {
        s_up += __shfl_xor_sync(0xffffffffu, s_up, o);
        s_un += __shfl_xor_sync(0xffffffffu, s_un, o);
        s_uu += __shfl_xor_sync(0xffffffffu, s_uu, o);
        s_pp += __shfl_xor_sync(0xffffffffu, s_pp, o);
        s_nn += __shfl_xor_sync(0xffffffffu, s_nn, o);
    }
    float iu = rsqrtf(s_uu);
    float ip = rsqrtf(s_pp);
    *(float2*)(g_un + (size_t)gw * EMB + lane * 2) = make_float2(u.x * iu, u.y * iu);
    *(float2*)(g_pn + (size_t)gw * EMB + lane * 2) = make_float2(p.x * ip, p.y * ip);
    if (lane == 0) {
        float d  = s_up - s_un;
        float sp = fmaxf(-d, 0.0f) + log1pf(expf(-fabsf(d)));  // softplus(-d)
        atomicAdd(&g_scal[0], sp);
        atomicAdd(&g_scal[1], s_uu + s_pp + s_nn);
    }
}

// ---------------- logits = (un @ pn^T) / tau : 64x64 tiles, K=64 -------------
__global__ __launch_bounds__(256) void k_gemm() {
    __shared__ float As[64][64];   // k-major
    __shared__ float Bs[64][64];
    int bi = blockIdx.y * 64, bj = blockIdx.x * 64;
    int tid = threadIdx.x;
    #pragma unroll
    for (int t = 0; t < 4; t++) {
        int vi = tid + t * 256;
        int r  = vi >> 4;
        int c  = (vi & 15) << 2;
        float4 a = *(const float4*)(g_un + (size_t)(bi + r) * EMB + c);
        As[c + 0][r] = a.x; As[c + 1][r] = a.y; As[c + 2][r] = a.z; As[c + 3][r] = a.w;
        float4 b = *(const float4*)(g_pn + (size_t)(bj + r) * EMB + c);
        Bs[c + 0][r] = b.x; Bs[c + 1][r] = b.y; Bs[c + 2][r] = b.z; Bs[c + 3][r] = b.w;
    }
    __syncthreads();
    int ty = tid >> 4, tx = tid & 15;
    float acc[4][4];
    #pragma unroll
    for (int a = 0; a < 4; a++)
        #pragma unroll
        for (int b = 0; b < 4; b++) acc[a][b] = 0.0f;
    #pragma unroll 8
    for (int k = 0; k < 64; k++) {
        float4 av = *(const float4*)&As[k][ty * 4];
        float4 bv = *(const float4*)&Bs[k][tx * 4];
        float a4[4] = {av.x, av.y, av.z, av.w};
        float b4[4] = {bv.x, bv.y, bv.z, bv.w};
        #pragma unroll
        for (int a = 0; a < 4; a++)
            #pragma unroll
            for (int b = 0; b < 4; b++) acc[a][b] += a4[a] * b4[b];
    }
    const float invTau = 1.0f / TAU;
    #pragma unroll
    for (int a = 0; a < 4; a++) {
        size_t rowoff = (size_t)(bi + ty * 4 + a) * BATCH + bj + tx * 4;
        float4 o = make_float4(acc[a][0] * invTau, acc[a][1] * invTau,
                               acc[a][2] * invTau, acc[a][3] * invTau);
        *(float4*)(g_logits + rowoff) = o;
    }
}

// ---------------- per-row logsumexp - diagonal -------------------------------
__global__ __launch_bounds__(256) void k_lse() {
    int row = blockIdx.x;
    const float* L = g_logits + (size_t)row * BATCH;
    float m = -1e30f, s = 0.0f;
    for (int j = threadIdx.x; j < BATCH; j += 256) {
        float x = L[j];
        if (x > m) { s = s * __expf(m - x) + 1.0f; m = x; }
        else       { s += __expf(x - m); }
    }
    __shared__ float sm[256], ss[256];
    sm[threadIdx.x] = m; ss[threadIdx.x] = s;
    __syncthreads();
    for (int o = 128; o; o >>= 1) {
        if (threadIdx.x < o) {
            float m2 = sm[threadIdx.x + o], s2 = ss[threadIdx.x + o];
            float m1 = sm[threadIdx.x],     s1 = ss[threadIdx.x];
            float M = fmaxf(m1, m2);
            ss[threadIdx.x] = s1 * __expf(m1 - M) + s2 * __expf(m2 - M);
            sm[threadIdx.x] = M;
        }
        __syncthreads();
    }
    if (threadIdx.x == 0) {
        float lse = sm[0] + logf(ss[0]);
        atomicAdd(&g_scal[2], lse - L[row]);
    }
}

// ---------------- finalize ---------------------------------------------------
__global__ void k_final(float* out) {
    float bpr = g_scal[0] / BATCH;
    float reg = 0.5f * g_scal[1] / BATCH * REG_LAMBDA;
    float na  = g_scal[2] / BATCH * SSL_LAMBDA;
    out[0] = bpr + reg + na;
}

// ---------------- host -------------------------------------------------------
extern "C" void kernel_launch(void* const* d_in, const int* in_sizes, int n_in,
                              void* d_out, int out_size) {
    const int*   user  = (const int*)d_in[0];
    const int*   pos   = (const int*)d_in[1];
    const int*   neg   = (const int*)d_in[2];
    const int*   arow  = (const int*)d_in[3];
    const int*   acol  = (const int*)d_in[4];
    const float* aval  = (const float*)d_in[5];
    const float* uw    = (const float*)d_in[6];
    const float* iw    = (const float*)d_in[7];
    float* out = (float*)d_out;

    float *e0, *e1, *e2, *e3;
    cudaGetSymbolAddress((void**)&e0, g_e0);
    cudaGetSymbolAddress((void**)&e1, g_e1);
    cudaGetSymbolAddress((void**)&e2, g_e2);
    cudaGetSymbolAddress((void**)&e3, g_e3);

    const int TB = 256;
    const int tab_blocks  = NVEC4 / TB;                    // 9375
    const int edge_blocks = (N_EDGES + TB - 1) / TB;       // 9375
    const int row_blocks  = (N_NODES * 32 + TB - 1) / TB;  // 18750 (warp/row)

    k_init<<<tab_blocks, TB>>>(uw, iw);
    k_hist<<<edge_blocks, TB>>>(arow);
    k_scan_block<<<SCAN_BLKS, TB>>>();
    k_scan_top<<<1, 1024>>>();
    k_scan_add<<<SCAN_BLKS, TB>>>();
    k_scatter<<<edge_blocks, TB>>>(arow, acol, aval);

    k_spmm<<<row_blocks, TB>>>(e0, e1);
    k_spmm<<<row_blocks, TB>>>(e1, e2);
    k_spmm<<<row_blocks, TB>>>(e2, e3);

    k_gather<<<(BATCH * 32) / TB, TB>>>(user, pos, neg);
    k_gemm<<<dim3(BATCH / 64, BATCH / 64), TB>>>();
    k_lse<<<BATCH, TB>>>();
    k_final<<<1, 1>>>(out);
}

// round 3
// speedup vs baseline: 1.4778x; 1.0532x over previous
#include <cuda_runtime.h>
#include <cuda_bf16.h>
#include <math.h>

#define NUM_USERS 100000
#define NUM_ITEMS 50000
#define N_NODES   150000
#define N_EDGES   2400000
#define EMB       64
#define BATCH     4096
#define TAU       0.2f
#define SSL_LAMBDA 0.1f
#define REG_LAMBDA 1e-4f

#define NVEC4      (N_NODES * EMB / 4)    // 2,400,000
#define NROWS_PAD  150016                 // 586 * 256
#define SCAN_BLKS  586

// ---------------- device scratch (static, no runtime allocation) -------------
__device__ __align__(16) __nv_bfloat16 g_b0[N_NODES * EMB];
__device__ __align__(16) __nv_bfloat16 g_b1[N_NODES * EMB];
__device__ __align__(16) __nv_bfloat16 g_b2[N_NODES * EMB];
__device__ __align__(16) __nv_bfloat16 g_b3[N_NODES * EMB];
__device__ __align__(16) float g_un[BATCH * EMB];
__device__ __align__(16) float g_pn[BATCH * EMB];
__device__ float g_rowsum[BATCH];
__device__ float g_scal[4];   // [0]=bpr, [1]=reg, [2]=na (log-sums minus diags)

// CSR build scratch
__device__ int   g_deg[NROWS_PAD];
__device__ int   g_scan[NROWS_PAD];
__device__ int   g_blksum[1024];
__device__ int   g_blkoff[1024];
__device__ int   g_rowptr[NROWS_PAD];
__device__ int   g_fill[NROWS_PAD];
__device__ int   g_ccol[N_EDGES];
__device__ float g_cval[N_EDGES];

// ---------------- init: b0 = bf16(concat(uw, iw)); zero counters -------------
__global__ __launch_bounds__(256) void k_init(const float* __restrict__ uw,
                                              const float* __restrict__ iw) {
    int i = blockIdx.x * blockDim.x + threadIdx.x;
    if (i < 4) g_scal[i] = 0.0f;
    if (i < BATCH) g_rowsum[i] = 0.0f;
    if (i < NROWS_PAD) g_deg[i] = 0;
    if (i >= NVEC4) return;
    const int UV = NUM_USERS * EMB / 4;
    float4 v = (i < UV) ? ((const float4*)uw)[i] : ((const float4*)iw)[i - UV];
    __nv_bfloat162 lo = __floats2bfloat162_rn(v.x, v.y);
    __nv_bfloat162 hi = __floats2bfloat162_rn(v.z, v.w);
    uint2 pk;
    pk.x = *reinterpret_cast<unsigned*>(&lo);
    pk.y = *reinterpret_cast<unsigned*>(&hi);
    ((uint2*)g_b0)[i] = pk;
}

// ---------------- CSR build ---------------------------------------------------
__global__ __launch_bounds__(256) void k_hist(const int* __restrict__ rows) {
    int e = blockIdx.x * blockDim.x + threadIdx.x;
    if (e < N_EDGES) atomicAdd(&g_deg[rows[e]], 1);
}

__global__ __launch_bounds__(256) void k_scan_block() {
    int b = blockIdx.x, i = b * 256 + threadIdx.x;
    int v = g_deg[i];
    int lane = threadIdx.x & 31, wid = threadIdx.x >> 5;
    int x = v;
    #pragma unroll
    for (int o = 1; o < 32; o <<= 1) {
        int y = __shfl_up_sync(0xffffffffu, x, o);
        if (lane >= o) x += y;
    }
    __shared__ int wsum[8];
    if (lane == 31) wsum[wid] = x;
    __syncthreads();
    if (threadIdx.x < 8) {
        int t = wsum[threadIdx.x];
        #pragma unroll
        for (int o = 1; o < 8; o <<= 1) {
            int y = __shfl_up_sync(0xffu, t, o);
            if (threadIdx.x >= o) t += y;
        }
        wsum[threadIdx.x] = t;
    }
    __syncthreads();
    int base = wid ? wsum[wid - 1] : 0;
    int incl = x + base;
    g_scan[i] = incl - v;
    if (threadIdx.x == 255) g_blksum[b] = incl;
}

__global__ __launch_bounds__(1024) void k_scan_top() {
    __shared__ int sh[1024];
    int tid = threadIdx.x;
    int v = (tid < SCAN_BLKS) ? g_blksum[tid] : 0;
    sh[tid] = v;
    __syncthreads();
    for (int o = 1; o < 1024; o <<= 1) {
        int t = (tid >= o) ? sh[tid - o] : 0;
        __syncthreads();
        sh[tid] += t;
        __syncthreads();
    }
    if (tid < SCAN_BLKS) g_blkoff[tid] = sh[tid] - v;
}

__global__ __launch_bounds__(256) void k_scan_add() {
    int i = blockIdx.x * blockDim.x + threadIdx.x;
    if (i >= NROWS_PAD) return;
    int start = g_scan[i] + g_blkoff[i >> 8];
    g_rowptr[i] = start;
    g_fill[i]   = start;
}

__global__ __launch_bounds__(256) void k_scatter(const int*   __restrict__ rows,
                                                 const int*   __restrict__ cols,
                                                 const float* __restrict__ vals) {
    int e = blockIdx.x * blockDim.x + threadIdx.x;
    if (e >= N_EDGES) return;
    int r = rows[e];
    int p = atomicAdd(&g_fill[r], 1);
    g_ccol[p] = cols[e];
    g_cval[p] = vals[e];
}

// ---------------- bf16 CSR SpMM: out[r] = sum_j val_j * in[col_j] ------------
// one warp per row, one bf16x2 per lane, fp32 accumulate, 4-way unrolled.
__global__ __launch_bounds__(256) void k_spmm(const __nv_bfloat16* __restrict__ b_in,
                                              __nv_bfloat16*       __restrict__ b_out) {
    int w = (blockIdx.x * 256 + threadIdx.x) >> 5;
    int lane = threadIdx.x & 31;
    if (w >= N_NODES) return;
    int start = g_rowptr[w];
    int deg   = g_deg[w];
    const int*   cc = g_ccol + start;
    const float* vv = g_cval + start;
    float ax = 0.f, ay = 0.f, bx = 0.f, by = 0.f;
    float cx = 0.f, cy = 0.f, dx = 0.f, dy = 0.f;
    int j = 0;
    for (; j + 4 <= deg; j += 4) {
        int   c0 = cc[j],   c1 = cc[j+1], c2 = cc[j+2], c3 = cc[j+3];
        float v0 = vv[j],   v1 = vv[j+1], v2 = vv[j+2], v3 = vv[j+3];
        float2 x0 = __bfloat1622float2(*(const __nv_bfloat162*)(b_in + (size_t)c0 * EMB + lane * 2));
        float2 x1 = __bfloat1622float2(*(const __nv_bfloat162*)(b_in + (size_t)c1 * EMB + lane * 2));
        float2 x2 = __bfloat1622float2(*(const __nv_bfloat162*)(b_in + (size_t)c2 * EMB + lane * 2));
        float2 x3 = __bfloat1622float2(*(const __nv_bfloat162*)(b_in + (size_t)c3 * EMB + lane * 2));
        ax += v0 * x0.x; ay += v0 * x0.y;
        bx += v1 * x1.x; by += v1 * x1.y;
        cx += v2 * x2.x; cy += v2 * x2.y;
        dx += v3 * x3.x; dy += v3 * x3.y;
    }
    for (; j < deg; j++) {
        int c = cc[j]; float v = vv[j];
        float2 x = __bfloat1622float2(*(const __nv_bfloat162*)(b_in + (size_t)c * EMB + lane * 2));
        ax += v * x.x; ay += v * x.y;
    }
    float rx = (ax + bx) + (cx + dx);
    float ry = (ay + by) + (cy + dy);
    *(__nv_bfloat162*)(b_out + (size_t)w * EMB + lane * 2) = __floats2bfloat162_rn(rx, ry);
}

// ---------------- gather: e0 from fp32 inputs + bf16 layers; BPR/reg/diag ----
__global__ __launch_bounds__(256) void k_gather(const int* __restrict__ user,
                                                const int* __restrict__ pos,
                                                const int* __restrict__ neg,
                                                const float* __restrict__ uw,
                                                const float* __restrict__ iw) {
    int gw   = (blockIdx.x * blockDim.x + threadIdx.x) >> 5;
    int lane = threadIdx.x & 31;
    if (gw >= BATCH) return;
    int ui = user[gw], pi = pos[gw], ni = neg[gw];
    size_t uoff = (size_t)ui * EMB + lane * 2;
    size_t poff = (size_t)pi * EMB + lane * 2;
    size_t noff = (size_t)ni * EMB + lane * 2;
    size_t uno = (size_t)ui * EMB + lane * 2;
    size_t pno = (size_t)(NUM_USERS + pi) * EMB + lane * 2;
    size_t nno = (size_t)(NUM_USERS + ni) * EMB + lane * 2;

    #define B2F(tab, off) __bfloat1622float2(*(const __nv_bfloat162*)((tab) + (off)))
    #define SUMALL(f32p, f32off, boff, dst) { \
        float2 base = *(const float2*)((f32p) + (f32off)); \
        float2 a1 = B2F(g_b1, boff), a2 = B2F(g_b2, boff), a3 = B2F(g_b3, boff); \
        dst.x = 0.25f * (base.x + a1.x + a2.x + a3.x); \
        dst.y = 0.25f * (base.y + a1.y + a2.y + a3.y); }
    float2 u, p, n;
    SUMALL(uw, uoff, uno, u);
    SUMALL(iw, poff, pno, p);
    SUMALL(iw, noff, nno, n);
    #undef SUMALL
    #undef B2F

    float s_up = u.x * p.x + u.y * p.y;
    float s_un = u.x * n.x + u.y * n.y;
    float s_uu = u.x * u.x + u.y * u.y;
    float s_pp = p.x * p.x + p.y * p.y;
    float s_nn = n.x * n.x + n.y * n.y;
    #pragma unroll
    for (int o = 16; o; o >>= 1) {
        s_up += __shfl_xor_sync(0xffffffffu, s_up, o);
        s_un += __shfl_xor_sync(0xffffffffu, s_un, o);
        s_uu += __shfl_xor_sync(0xffffffffu, s_uu, o);
        s_pp += __shfl_xor_sync(0xffffffffu, s_pp, o);
        s_nn += __shfl_xor_sync(0xffffffffu, s_nn, o);
    }
    float iu = rsqrtf(s_uu);
    float ip = rsqrtf(s_pp);
    *(float2*)(g_un + (size_t)gw * EMB + lane * 2) = make_float2(u.x * iu, u.y * iu);
    *(float2*)(g_pn + (size_t)gw * EMB + lane * 2) = make_float2(p.x * ip, p.y * ip);
    if (lane == 0) {
        float d  = s_up - s_un;
        float sp = fmaxf(-d, 0.0f) + log1pf(expf(-fabsf(d)));  // softplus(-d)
        atomicAdd(&g_scal[0], sp);
        atomicAdd(&g_scal[1], s_uu + s_pp + s_nn);
        float diag = s_up * iu * ip * (1.0f / TAU);             // exact pos logit
        atomicAdd(&g_scal[2], -diag);
    }
}

// ---------------- fused GEMM + exp row-sum: rowsum[i] += sum_j exp(l_ij) -----
__global__ __launch_bounds__(256) void k_gemm() {
    __shared__ float As[64][64];   // k-major
    __shared__ float Bs[64][64];
    int bi = blockIdx.y * 64, bj = blockIdx.x * 64;
    int tid = threadIdx.x;
    #pragma unroll
    for (int t = 0; t < 4; t++) {
        int vi = tid + t * 256;
        int r  = vi >> 4;
        int c  = (vi & 15) << 2;
        float4 a = *(const float4*)(g_un + (size_t)(bi + r) * EMB + c);
        As[c + 0][r] = a.x; As[c + 1][r] = a.y; As[c + 2][r] = a.z; As[c + 3][r] = a.w;
        float4 b = *(const float4*)(g_pn + (size_t)(bj + r) * EMB + c);
        Bs[c + 0][r] = b.x; Bs[c + 1][r] = b.y; Bs[c + 2][r] = b.z; Bs[c + 3][r] = b.w;
    }
    __syncthreads();
    int ty = tid >> 4, tx = tid & 15;
    float acc[4][4];
    #pragma unroll
    for (int a = 0; a < 4; a++)
        #pragma unroll
        for (int b = 0; b < 4; b++) acc[a][b] = 0.0f;
    #pragma unroll 8
    for (int k = 0; k < 64; k++) {
        float4 av = *(const float4*)&As[k][ty * 4];
        float4 bv = *(const float4*)&Bs[k][tx * 4];
        float a4[4] = {av.x, av.y, av.z, av.w};
        float b4[4] = {bv.x, bv.y, bv.z, bv.w};
        #pragma unroll
        for (int a = 0; a < 4; a++)
            #pragma unroll
            for (int b = 0; b < 4; b++) acc[a][b] += a4[a] * b4[b];
    }
    // exp and per-row partial sums (logits bounded by |1/TAU| = 5: no max needed)
    const float invTau = 1.0f / TAU;
    float rp[4];
    #pragma unroll
    for (int a = 0; a < 4; a++) {
        rp[a] = __expf(acc[a][0] * invTau) + __expf(acc[a][1] * invTau)
              + __expf(acc[a][2] * invTau) + __expf(acc[a][3] * invTau);
    }
    // reduce across tx (low 4 lane bits)
    #pragma unroll
    for (int o = 1; o < 16; o <<= 1) {
        #pragma unroll
        for (int a = 0; a < 4; a++)
            rp[a] += __shfl_xor_sync(0xffffffffu, rp[a], o);
    }
    if (tx == 0) {
        #pragma unroll
        for (int a = 0; a < 4; a++)
            atomicAdd(&g_rowsum[bi + ty * 4 + a], rp[a]);
    }
}

// ---------------- sum of log(rowsum) into g_scal[2] --------------------------
__global__ __launch_bounds__(256) void k_logsum() {
    int i = blockIdx.x * blockDim.x + threadIdx.x;
    float v = (i < BATCH) ? logf(g_rowsum[i]) : 0.0f;
    #pragma unroll
    for (int o = 16; o; o >>= 1) v += __shfl_xor_sync(0xffffffffu, v, o);
    __shared__ float ws[8];
    int lane = threadIdx.x & 31, wid = threadIdx.x >> 5;
    if (lane == 0) ws[wid] = v;
    __syncthreads();
    if (threadIdx.x == 0) {
        float s = 0.f;
        #pragma unroll
        for (int k = 0; k < 8; k++) s += ws[k];
        atomicAdd(&g_scal[2], s);
    }
}

// ---------------- finalize ---------------------------------------------------
__global__ void k_final(float* out) {
    float bpr = g_scal[0] / BATCH;
    float reg = 0.5f * g_scal[1] / BATCH * REG_LAMBDA;
    float na  = g_scal[2] / BATCH * SSL_LAMBDA;
    out[0] = bpr + reg + na;
}

// ---------------- host -------------------------------------------------------
extern "C" void kernel_launch(void* const* d_in, const int* in_sizes, int n_in,
                              void* d_out, int out_size) {
    const int*   user  = (const int*)d_in[0];
    const int*   pos   = (const int*)d_in[1];
    const int*   neg   = (const int*)d_in[2];
    const int*   arow  = (const int*)d_in[3];
    const int*   acol  = (const int*)d_in[4];
    const float* aval  = (const float*)d_in[5];
    const float* uw    = (const float*)d_in[6];
    const float* iw    = (const float*)d_in[7];
    float* out = (float*)d_out;

    __nv_bfloat16 *b0, *b1, *b2, *b3;
    cudaGetSymbolAddress((void**)&b0, g_b0);
    cudaGetSymbolAddress((void**)&b1, g_b1);
    cudaGetSymbolAddress((void**)&b2, g_b2);
    cudaGetSymbolAddress((void**)&b3, g_b3);

    const int TB = 256;
    const int tab_blocks  = NVEC4 / TB;                    // 9375
    const int edge_blocks = (N_EDGES + TB - 1) / TB;       // 9375
    const int row_blocks  = (N_NODES * 32 + TB - 1) / TB;  // 18750

    k_init<<<tab_blocks, TB>>>(uw, iw);
    k_hist<<<edge_blocks, TB>>>(arow);
    k_scan_block<<<SCAN_BLKS, TB>>>();
    k_scan_top<<<1, 1024>>>();
    k_scan_add<<<SCAN_BLKS, TB>>>();
    k_scatter<<<edge_blocks, TB>>>(arow, acol, aval);

    k_spmm<<<row_blocks, TB>>>(b0, b1);
    k_spmm<<<row_blocks, TB>>>(b1, b2);
    k_spmm<<<row_blocks, TB>>>(b2, b3);

    k_gather<<<(BATCH * 32) / TB, TB>>>(user, pos, neg, uw, iw);
    k_gemm<<<dim3(BATCH / 64, BATCH / 64), TB>>>();
    k_logsum<<<BATCH / TB, TB>>>();
    k_final<<<1, 1>>>(out);
}

// round 4
// speedup vs baseline: 2.1395x; 1.4478x over previous
#include <cuda_runtime.h>
#include <cuda_bf16.h>
#include <mma.h>
#include <math.h>

using namespace nvcuda;

#define NUM_USERS 100000
#define NUM_ITEMS 50000
#define N_NODES   150000
#define N_EDGES   2400000
#define EMB       64
#define BATCH     4096
#define TAU       0.2f
#define SSL_LAMBDA 0.1f
#define REG_LAMBDA 1e-4f

#define NVEC4      (N_NODES * EMB / 4)    // 2,400,000 == N_EDGES
#define NROWS_PAD  150016                 // 586 * 256
#define SCAN_BLKS  586

// ---------------- device scratch (static, zero-initialized at load) ----------
__device__ __align__(16) __nv_bfloat16 g_b0[N_NODES * EMB];
__device__ __align__(16) __nv_bfloat16 g_b1[N_NODES * EMB];
__device__ __align__(16) __nv_bfloat16 g_b2[N_NODES * EMB];
__device__ __align__(16) __nv_bfloat16 g_b3[N_NODES * EMB];
__device__ __align__(16) __nv_bfloat16 g_unb[BATCH * EMB];
__device__ __align__(16) __nv_bfloat16 g_pnb[BATCH * EMB];
__device__ float g_rowsum[BATCH];   // zeroed at end of k_logsum each run
__device__ float g_scal[4];         // zeroed at end of k_final each run
__device__ int   g_ctr;             // zeroed at end of k_final each run

// CSR scratch
__device__ int   g_deg[NROWS_PAD];  // zeroed at end of k_gemm each run
__device__ int   g_rowptr[NROWS_PAD];
__device__ int   g_fill[NROWS_PAD];
__device__ int   g_ccol[N_EDGES];
__device__ float g_cval[N_EDGES];

// ---------------- combo: b0 = bf16(concat(uw,iw)) AND degree histogram -------
// NVEC4 == N_EDGES == 2,400,000, so one grid covers both jobs exactly.
__global__ __launch_bounds__(256) void k_combo(const float* __restrict__ uw,
                                               const float* __restrict__ iw,
                                               const int*   __restrict__ rows) {
    int i = blockIdx.x * blockDim.x + threadIdx.x;
    const int UV = NUM_USERS * EMB / 4;
    float4 v = (i < UV) ? ((const float4*)uw)[i] : ((const float4*)iw)[i - UV];
    __nv_bfloat162 lo = __floats2bfloat162_rn(v.x, v.y);
    __nv_bfloat162 hi = __floats2bfloat162_rn(v.z, v.w);
    uint2 pk;
    pk.x = *reinterpret_cast<unsigned*>(&lo);
    pk.y = *reinterpret_cast<unsigned*>(&hi);
    ((uint2*)g_b0)[i] = pk;
    atomicAdd(&g_deg[rows[i]], 1);       // g_deg pre-zeroed (static / end of prior run)
}

// ---------------- CSR offsets: block scan + atomic base ----------------------
__global__ __launch_bounds__(256) void k_csr() {
    int i = blockIdx.x * 256 + threadIdx.x;
    int v = g_deg[i];
    int lane = threadIdx.x & 31, wid = threadIdx.x >> 5;
    int x = v;
    #pragma unroll
    for (int o = 1; o < 32; o <<= 1) {
        int y = __shfl_up_sync(0xffffffffu, x, o);
        if (lane >= o) x += y;
    }
    __shared__ int wsum[8];
    __shared__ int base_sh;
    if (lane == 31) wsum[wid] = x;
    __syncthreads();
    if (threadIdx.x < 8) {
        int t = wsum[threadIdx.x];
        #pragma unroll
        for (int o = 1; o < 8; o <<= 1) {
            int y = __shfl_up_sync(0xffu, t, o);
            if (threadIdx.x >= o) t += y;
        }
        wsum[threadIdx.x] = t;
    }
    __syncthreads();
    int incl = x + (wid ? wsum[wid - 1] : 0);
    if (threadIdx.x == 255) base_sh = atomicAdd(&g_ctr, incl);  // incl==block total
    __syncthreads();
    int start = base_sh + incl - v;
    g_rowptr[i] = start;
    g_fill[i]   = start;
}

__global__ __launch_bounds__(256) void k_scatter(const int*   __restrict__ rows,
                                                 const int*   __restrict__ cols,
                                                 const float* __restrict__ vals) {
    int e = blockIdx.x * blockDim.x + threadIdx.x;
    if (e >= N_EDGES) return;
    int r = rows[e];
    int p = atomicAdd(&g_fill[r], 1);
    g_ccol[p] = cols[e];
    g_cval[p] = vals[e];
}

// ---------------- bf16 CSR SpMM, warp/row, unroll-8 (MLP=8) ------------------
__global__ __launch_bounds__(256) void k_spmm(const __nv_bfloat16* __restrict__ b_in,
                                              __nv_bfloat16*       __restrict__ b_out) {
    int w = (blockIdx.x * 256 + threadIdx.x) >> 5;
    int lane = threadIdx.x & 31;
    if (w >= N_NODES) return;
    int start = g_rowptr[w];
    int deg   = g_deg[w];
    const int*   cc = g_ccol + start;
    const float* vv = g_cval + start;
    float a0x = 0.f, a0y = 0.f, a1x = 0.f, a1y = 0.f;
    float a2x = 0.f, a2y = 0.f, a3x = 0.f, a3y = 0.f;
    int j = 0;
    for (; j + 8 <= deg; j += 8) {
        int   c[8]; float v[8];
        #pragma unroll
        for (int q = 0; q < 8; q++) { c[q] = cc[j + q]; v[q] = vv[j + q]; }
        float2 x[8];
        #pragma unroll
        for (int q = 0; q < 8; q++)
            x[q] = __bfloat1622float2(*(const __nv_bfloat162*)(b_in + (size_t)c[q] * EMB + lane * 2));
        a0x += v[0]*x[0].x; a0y += v[0]*x[0].y;  a1x += v[1]*x[1].x; a1y += v[1]*x[1].y;
        a2x += v[2]*x[2].x; a2y += v[2]*x[2].y;  a3x += v[3]*x[3].x; a3y += v[3]*x[3].y;
        a0x += v[4]*x[4].x; a0y += v[4]*x[4].y;  a1x += v[5]*x[5].x; a1y += v[5]*x[5].y;
        a2x += v[6]*x[6].x; a2y += v[6]*x[6].y;  a3x += v[7]*x[7].x; a3y += v[7]*x[7].y;
    }
    for (; j + 4 <= deg; j += 4) {
        int   c[4]; float v[4];
        #pragma unroll
        for (int q = 0; q < 4; q++) { c[q] = cc[j + q]; v[q] = vv[j + q]; }
        float2 x[4];
        #pragma unroll
        for (int q = 0; q < 4; q++)
            x[q] = __bfloat1622float2(*(const __nv_bfloat162*)(b_in + (size_t)c[q] * EMB + lane * 2));
        a0x += v[0]*x[0].x; a0y += v[0]*x[0].y;  a1x += v[1]*x[1].x; a1y += v[1]*x[1].y;
        a2x += v[2]*x[2].x; a2y += v[2]*x[2].y;  a3x += v[3]*x[3].x; a3y += v[3]*x[3].y;
    }
    for (; j < deg; j++) {
        int c = cc[j]; float v = vv[j];
        float2 x = __bfloat1622float2(*(const __nv_bfloat162*)(b_in + (size_t)c * EMB + lane * 2));
        a0x += v * x.x; a0y += v * x.y;
    }
    float rx = (a0x + a1x) + (a2x + a3x);
    float ry = (a0y + a1y) + (a2y + a3y);
    *(__nv_bfloat162*)(b_out + (size_t)w * EMB + lane * 2) = __floats2bfloat162_rn(rx, ry);
}

// ---------------- gather: fp32 e0 + bf16 layers; BPR/reg/diag; bf16 un/pn ----
__global__ __launch_bounds__(256) void k_gather(const int* __restrict__ user,
                                                const int* __restrict__ pos,
                                                const int* __restrict__ neg,
                                                const float* __restrict__ uw,
                                                const float* __restrict__ iw) {
    int gw   = (blockIdx.x * blockDim.x + threadIdx.x) >> 5;
    int lane = threadIdx.x & 31;
    if (gw >= BATCH) return;
    int ui = user[gw], pi = pos[gw], ni = neg[gw];
    size_t uoff = (size_t)ui * EMB + lane * 2;
    size_t poff = (size_t)pi * EMB + lane * 2;
    size_t noff = (size_t)ni * EMB + lane * 2;
    size_t uno  = (size_t)ui * EMB + lane * 2;
    size_t pno  = (size_t)(NUM_USERS + pi) * EMB + lane * 2;
    size_t nno  = (size_t)(NUM_USERS + ni) * EMB + lane * 2;

    #define B2F(tab, off) __bfloat1622float2(*(const __nv_bfloat162*)((tab) + (off)))
    #define SUMALL(f32p, f32off, boff, dst) { \
        float2 base = *(const float2*)((f32p) + (f32off)); \
        float2 a1 = B2F(g_b1, boff), a2 = B2F(g_b2, boff), a3 = B2F(g_b3, boff); \
        dst.x = 0.25f * (base.x + a1.x + a2.x + a3.x); \
        dst.y = 0.25f * (base.y + a1.y + a2.y + a3.y); }
    float2 u, p, n;
    SUMALL(uw, uoff, uno, u);
    SUMALL(iw, poff, pno, p);
    SUMALL(iw, noff, nno, n);
    #undef SUMALL
    #undef B2F

    float s_up = u.x * p.x + u.y * p.y;
    float s_un = u.x * n.x + u.y * n.y;
    float s_uu = u.x * u.x + u.y * u.y;
    float s_pp = p.x * p.x + p.y * p.y;
    float s_nn = n.x * n.x + n.y * n.y;
    #pragma unroll
    for (int o = 16; o; o >>= 1) {
        s_up += __shfl_xor_sync(0xffffffffu, s_up, o);
        s_un += __shfl_xor_sync(0xffffffffu, s_un, o);
        s_uu += __shfl_xor_sync(0xffffffffu, s_uu, o);
        s_pp += __shfl_xor_sync(0xffffffffu, s_pp, o);
        s_nn += __shfl_xor_sync(0xffffffffu, s_nn, o);
    }
    float iu = rsqrtf(s_uu);
    float ip = rsqrtf(s_pp);
    *(__nv_bfloat162*)(g_unb + (size_t)gw * EMB + lane * 2) = __floats2bfloat162_rn(u.x * iu, u.y * iu);
    *(__nv_bfloat162*)(g_pnb + (size_t)gw * EMB + lane * 2) = __floats2bfloat162_rn(p.x * ip, p.y * ip);
    if (lane == 0) {
        float d  = s_up - s_un;
        float sp = fmaxf(-d, 0.0f) + log1pf(expf(-fabsf(d)));  // softplus(-d)
        atomicAdd(&g_scal[0], sp);
        atomicAdd(&g_scal[1], s_uu + s_pp + s_nn);
        float diag = s_up * iu * ip * (1.0f / TAU);             // exact pos logit
        atomicAdd(&g_scal[2], -diag);
    }
}

// ---------------- WMMA bf16 GEMM (64x64 tile) fused with exp row-sum ---------
#define LDT 80   // shared leading dim (bf16 elems), 160B rows: 16B-aligned vec ops
__global__ __launch_bounds__(256) void k_gemm() {
    __shared__ __nv_bfloat16 Asm[64 * LDT];
    __shared__ __nv_bfloat16 Bsm[64 * LDT];
    __shared__ float         Csm[64 * 64];
    int bi = blockIdx.y * 64, bj = blockIdx.x * 64;
    int tid = threadIdx.x;

    // housekeeping: re-zero g_deg for the next run (first 586 blocks)
    int bid = blockIdx.y * 64 + blockIdx.x;
    if (bid < SCAN_BLKS) g_deg[bid * 256 + tid] = 0;

    // load 64x64 bf16 tiles (8 bf16 = 16B per thread per pass, 2 passes)
    #pragma unroll
    for (int pass = 0; pass < 2; pass++) {
        int row = pass * 32 + (tid >> 3);
        int col = (tid & 7) * 8;
        *(uint4*)(Asm + row * LDT + col) = *(const uint4*)(g_unb + (size_t)(bi + row) * EMB + col);
        *(uint4*)(Bsm + row * LDT + col) = *(const uint4*)(g_pnb + (size_t)(bj + row) * EMB + col);
    }
    __syncthreads();

    int wid = tid >> 5;
    int frow = wid >> 1;            // 0..3  (16-row band)
    int fcol0 = (wid & 1) * 2;      // 0 or 2 (two 16-col bands)
    wmma::fragment<wmma::accumulator, 16, 16, 16, float> acc0, acc1;
    wmma::fill_fragment(acc0, 0.0f);
    wmma::fill_fragment(acc1, 0.0f);
    #pragma unroll
    for (int kk = 0; kk < 64; kk += 16) {
        wmma::fragment<wmma::matrix_a, 16, 16, 16, __nv_bfloat16, wmma::row_major> af;
        wmma::fragment<wmma::matrix_b, 16, 16, 16, __nv_bfloat16, wmma::col_major> bf0, bf1;
        wmma::load_matrix_sync(af, Asm + frow * 16 * LDT + kk, LDT);
        wmma::load_matrix_sync(bf0, Bsm + (fcol0 + 0) * 16 * LDT + kk, LDT);
        wmma::load_matrix_sync(bf1, Bsm + (fcol0 + 1) * 16 * LDT + kk, LDT);
        wmma::mma_sync(acc0, af, bf0, acc0);
        wmma::mma_sync(acc1, af, bf1, acc1);
    }
    wmma::store_matrix_sync(Csm + frow * 16 * 64 + (fcol0 + 0) * 16, acc0, 64, wmma::mem_row_major);
    wmma::store_matrix_sync(Csm + frow * 16 * 64 + (fcol0 + 1) * 16, acc1, 64, wmma::mem_row_major);
    __syncthreads();

    // exp + per-row sum (logits bounded by 1/TAU=5: no max shift needed)
    const float invTau = 1.0f / TAU;
    int row = tid >> 2;
    int seg = (tid & 3) * 16;
    const float* Crow = Csm + row * 64 + seg;
    float s = 0.0f;
    #pragma unroll
    for (int q = 0; q < 16; q++) s += __expf(Crow[q] * invTau);
    s += __shfl_xor_sync(0xffffffffu, s, 1);
    s += __shfl_xor_sync(0xffffffffu, s, 2);
    if ((tid & 3) == 0) atomicAdd(&g_rowsum[bi + row], s);
}

// ---------------- sum of log(rowsum); zero rowsum for next run ---------------
__global__ __launch_bounds__(256) void k_logsum() {
    int i = blockIdx.x * blockDim.x + threadIdx.x;
    float v = logf(g_rowsum[i]);
    g_rowsum[i] = 0.0f;
    #pragma unroll
    for (int o = 16; o; o >>= 1) v += __shfl_xor_sync(0xffffffffu, v, o);
    __shared__ float ws[8];
    int lane = threadIdx.x & 31, wid = threadIdx.x >> 5;
    if (lane == 0) ws[wid] = v;
    __syncthreads();
    if (threadIdx.x == 0) {
        float s = 0.f;
        #pragma unroll
        for (int k = 0; k < 8; k++) s += ws[k];
        atomicAdd(&g_scal[2], s);
    }
}

// ---------------- finalize; reset accumulators for next run ------------------
__global__ void k_final(float* out) {
    float bpr = g_scal[0] / BATCH;
    float reg = 0.5f * g_scal[1] / BATCH * REG_LAMBDA;
    float na  = g_scal[2] / BATCH * SSL_LAMBDA;
    out[0] = bpr + reg + na;
    g_scal[0] = 0.f; g_scal[1] = 0.f; g_scal[2] = 0.f; g_scal[3] = 0.f;
    g_ctr = 0;
}

// ---------------- host -------------------------------------------------------
extern "C" void kernel_launch(void* const* d_in, const int* in_sizes, int n_in,
                              void* d_out, int out_size) {
    const int*   user  = (const int*)d_in[0];
    const int*   pos   = (const int*)d_in[1];
    const int*   neg   = (const int*)d_in[2];
    const int*   arow  = (const int*)d_in[3];
    const int*   acol  = (const int*)d_in[4];
    const float* aval  = (const float*)d_in[5];
    const float* uw    = (const float*)d_in[6];
    const float* iw    = (const float*)d_in[7];
    float* out = (float*)d_out;

    __nv_bfloat16 *b0, *b1, *b2, *b3;
    cudaGetSymbolAddress((void**)&b0, g_b0);
    cudaGetSymbolAddress((void**)&b1, g_b1);
    cudaGetSymbolAddress((void**)&b2, g_b2);
    cudaGetSymbolAddress((void**)&b3, g_b3);

    const int TB = 256;
    const int edge_blocks = N_EDGES / TB;                  // 9375
    const int row_blocks  = (N_NODES * 32 + TB - 1) / TB;  // 18750

    k_combo<<<edge_blocks, TB>>>(uw, iw, arow);            // 1
    k_csr<<<SCAN_BLKS, TB>>>();                            // 2
    k_scatter<<<edge_blocks, TB>>>(arow, acol, aval);      // 3
    k_spmm<<<row_blocks, TB>>>(b0, b1);                    // 4  <- ncu lands here
    k_spmm<<<row_blocks, TB>>>(b1, b2);                    // 5
    k_spmm<<<row_blocks, TB>>>(b2, b3);                    // 6
    k_gather<<<(BATCH * 32) / TB, TB>>>(user, pos, neg, uw, iw);   // 7
    k_gemm<<<dim3(BATCH / 64, BATCH / 64), TB>>>();        // 8
    k_logsum<<<BATCH / TB, TB>>>();                        // 9
    k_final<<<1, 1>>>(out);                                // 10
}

// round 5
// speedup vs baseline: 2.4430x; 1.1419x over previous
#include <cuda_runtime.h>
#include <cuda_bf16.h>
#include <mma.h>
#include <math.h>

using namespace nvcuda;

#define NUM_USERS 100000
#define NUM_ITEMS 50000
#define N_NODES   150000
#define N_EDGES   2400000
#define EMB       64
#define BATCH     4096
#define TAU       0.2f
#define SSL_LAMBDA 0.1f
#define REG_LAMBDA 1e-4f

#define NVEC4      (N_NODES * EMB / 4)    // 2,400,000 == N_EDGES
#define NROWS_PAD  150016                 // 586 * 256
#define SCAN_BLKS  586

// ---------------- device scratch (static, zero-initialized at load) ----------
__device__ __align__(16) __nv_bfloat16 g_b0[N_NODES * EMB];
__device__ __align__(16) __nv_bfloat16 g_b1[N_NODES * EMB];
__device__ __align__(16) __nv_bfloat16 g_b2[N_NODES * EMB];
__device__ __align__(16) __nv_bfloat16 g_b3[N_NODES * EMB];
__device__ __align__(16) __nv_bfloat16 g_unb[BATCH * EMB];
__device__ __align__(16) __nv_bfloat16 g_pnb[BATCH * EMB];
__device__ float g_rowsum[BATCH];   // zeroed at end of k_logsum each run
__device__ float g_scal[4];         // zeroed at end of k_final each run
__device__ int   g_ctr;             // zeroed at end of k_final each run

// CSR scratch
__device__ int   g_deg[NROWS_PAD];  // zeroed inside k_gemm each run
__device__ int   g_rowptr[NROWS_PAD];
__device__ int   g_fill[NROWS_PAD];
__device__ __align__(8) int2 g_epack[N_EDGES];   // {col, val bits}

// ---------------- combo: b0 = bf16(concat(uw,iw)) AND degree histogram -------
__global__ __launch_bounds__(256) void k_combo(const float* __restrict__ uw,
                                               const float* __restrict__ iw,
                                               const int*   __restrict__ rows) {
    int i = blockIdx.x * blockDim.x + threadIdx.x;
    const int UV = NUM_USERS * EMB / 4;
    float4 v = (i < UV) ? ((const float4*)uw)[i] : ((const float4*)iw)[i - UV];
    __nv_bfloat162 lo = __floats2bfloat162_rn(v.x, v.y);
    __nv_bfloat162 hi = __floats2bfloat162_rn(v.z, v.w);
    uint2 pk;
    pk.x = *reinterpret_cast<unsigned*>(&lo);
    pk.y = *reinterpret_cast<unsigned*>(&hi);
    ((uint2*)g_b0)[i] = pk;
    atomicAdd(&g_deg[rows[i]], 1);
}

// ---------------- CSR offsets: block scan + atomic base ----------------------
__global__ __launch_bounds__(256) void k_csr() {
    int i = blockIdx.x * 256 + threadIdx.x;
    int v = g_deg[i];
    int lane = threadIdx.x & 31, wid = threadIdx.x >> 5;
    int x = v;
    #pragma unroll
    for (int o = 1; o < 32; o <<= 1) {
        int y = __shfl_up_sync(0xffffffffu, x, o);
        if (lane >= o) x += y;
    }
    __shared__ int wsum[8];
    __shared__ int base_sh;
    if (lane == 31) wsum[wid] = x;
    __syncthreads();
    if (threadIdx.x < 8) {
        int t = wsum[threadIdx.x];
        #pragma unroll
        for (int o = 1; o < 8; o <<= 1) {
            int y = __shfl_up_sync(0xffu, t, o);
            if (threadIdx.x >= o) t += y;
        }
        wsum[threadIdx.x] = t;
    }
    __syncthreads();
    int incl = x + (wid ? wsum[wid - 1] : 0);
    if (threadIdx.x == 255) base_sh = atomicAdd(&g_ctr, incl);
    __syncthreads();
    int start = base_sh + incl - v;
    g_rowptr[i] = start;
    g_fill[i]   = start;
}

__global__ __launch_bounds__(256) void k_scatter(const int*   __restrict__ rows,
                                                 const int*   __restrict__ cols,
                                                 const float* __restrict__ vals) {
    int e = blockIdx.x * blockDim.x + threadIdx.x;
    if (e >= N_EDGES) return;
    int r = rows[e];
    int p = atomicAdd(&g_fill[r], 1);
    int2 pk;
    pk.x = cols[e];
    pk.y = __float_as_int(vals[e]);
    g_epack[p] = pk;
}

// ---------------- bf16 CSR SpMM: warp/row, 2 neighbors per iteration ---------
// half-warps process alternating neighbors; each lane owns 4 dims (8B loads).
__global__ __launch_bounds__(256) void k_spmm(const __nv_bfloat16* __restrict__ b_in,
                                              __nv_bfloat16*       __restrict__ b_out) {
    int w = (blockIdx.x * 256 + threadIdx.x) >> 5;
    int lane = threadIdx.x & 31;
    if (w >= N_NODES) return;
    int half = lane >> 4;            // 0 or 1
    int sub  = lane & 15;            // dim group: dims sub*4 .. sub*4+3
    int start = g_rowptr[w];
    int deg   = g_deg[w];
    const int2* ep = g_epack + start;

    float4 acc = make_float4(0.f, 0.f, 0.f, 0.f);
    int j = 0;
    for (; j + 8 <= deg; j += 8) {
        #pragma unroll
        for (int q = 0; q < 4; q++) {
            int2 e = ep[j + q * 2 + half];
            float v = __int_as_float(e.y);
            unsigned off = (unsigned)e.x * EMB + sub * 4;
            uint2 raw = *(const uint2*)(b_in + off);
            float2 x0 = __bfloat1622float2(*reinterpret_cast<__nv_bfloat162*>(&raw.x));
            float2 x1 = __bfloat1622float2(*reinterpret_cast<__nv_bfloat162*>(&raw.y));
            acc.x += v * x0.x; acc.y += v * x0.y;
            acc.z += v * x1.x; acc.w += v * x1.y;
        }
    }
    for (; j < deg; j += 2) {
        int jj = j + half;
        if (jj < deg) {
            int2 e = ep[jj];
            float v = __int_as_float(e.y);
            unsigned off = (unsigned)e.x * EMB + sub * 4;
            uint2 raw = *(const uint2*)(b_in + off);
            float2 x0 = __bfloat1622float2(*reinterpret_cast<__nv_bfloat162*>(&raw.x));
            float2 x1 = __bfloat1622float2(*reinterpret_cast<__nv_bfloat162*>(&raw.y));
            acc.x += v * x0.x; acc.y += v * x0.y;
            acc.z += v * x1.x; acc.w += v * x1.y;
        }
    }
    // combine the two halves
    acc.x += __shfl_xor_sync(0xffffffffu, acc.x, 16);
    acc.y += __shfl_xor_sync(0xffffffffu, acc.y, 16);
    acc.z += __shfl_xor_sync(0xffffffffu, acc.z, 16);
    acc.w += __shfl_xor_sync(0xffffffffu, acc.w, 16);
    if (half == 0) {
        __nv_bfloat162 lo = __floats2bfloat162_rn(acc.x, acc.y);
        __nv_bfloat162 hi = __floats2bfloat162_rn(acc.z, acc.w);
        uint2 pk;
        pk.x = *reinterpret_cast<unsigned*>(&lo);
        pk.y = *reinterpret_cast<unsigned*>(&hi);
        *(uint2*)(b_out + (size_t)w * EMB + sub * 4) = pk;
    }
}

// ---------------- gather: fp32 e0 + bf16 layers; BPR/reg/diag; bf16 un/pn ----
__global__ __launch_bounds__(256) void k_gather(const int* __restrict__ user,
                                                const int* __restrict__ pos,
                                                const int* __restrict__ neg,
                                                const float* __restrict__ uw,
                                                const float* __restrict__ iw) {
    int gw   = (blockIdx.x * blockDim.x + threadIdx.x) >> 5;
    int lane = threadIdx.x & 31;
    if (gw >= BATCH) return;
    int ui = user[gw], pi = pos[gw], ni = neg[gw];
    size_t uoff = (size_t)ui * EMB + lane * 2;
    size_t poff = (size_t)pi * EMB + lane * 2;
    size_t noff = (size_t)ni * EMB + lane * 2;
    size_t uno  = (size_t)ui * EMB + lane * 2;
    size_t pno  = (size_t)(NUM_USERS + pi) * EMB + lane * 2;
    size_t nno  = (size_t)(NUM_USERS + ni) * EMB + lane * 2;

    #define B2F(tab, off) __bfloat1622float2(*(const __nv_bfloat162*)((tab) + (off)))
    #define SUMALL(f32p, f32off, boff, dst) { \
        float2 base = *(const float2*)((f32p) + (f32off)); \
        float2 a1 = B2F(g_b1, boff), a2 = B2F(g_b2, boff), a3 = B2F(g_b3, boff); \
        dst.x = 0.25f * (base.x + a1.x + a2.x + a3.x); \
        dst.y = 0.25f * (base.y + a1.y + a2.y + a3.y); }
    float2 u, p, n;
    SUMALL(uw, uoff, uno, u);
    SUMALL(iw, poff, pno, p);
    SUMALL(iw, noff, nno, n);
    #undef SUMALL
    #undef B2F

    float s_up = u.x * p.x + u.y * p.y;
    float s_un = u.x * n.x + u.y * n.y;
    float s_uu = u.x * u.x + u.y * u.y;
    float s_pp = p.x * p.x + p.y * p.y;
    float s_nn = n.x * n.x + n.y * n.y;
    #pragma unroll
    for (int o = 16; o; o >>= 1) {
        s_up += __shfl_xor_sync(0xffffffffu, s_up, o);
        s_un += __shfl_xor_sync(0xffffffffu, s_un, o);
        s_uu += __shfl_xor_sync(0xffffffffu, s_uu, o);
        s_pp += __shfl_xor_sync(0xffffffffu, s_pp, o);
        s_nn += __shfl_xor_sync(0xffffffffu, s_nn, o);
    }
    float iu = rsqrtf(s_uu);
    float ip = rsqrtf(s_pp);
    *(__nv_bfloat162*)(g_unb + (size_t)gw * EMB + lane * 2) = __floats2bfloat162_rn(u.x * iu, u.y * iu);
    *(__nv_bfloat162*)(g_pnb + (size_t)gw * EMB + lane * 2) = __floats2bfloat162_rn(p.x * ip, p.y * ip);
    if (lane == 0) {
        float d  = s_up - s_un;
        float sp = fmaxf(-d, 0.0f) + log1pf(expf(-fabsf(d)));  // softplus(-d)
        atomicAdd(&g_scal[0], sp);
        atomicAdd(&g_scal[1], s_uu + s_pp + s_nn);
        float diag = s_up * iu * ip * (1.0f / TAU);             // exact pos logit
        atomicAdd(&g_scal[2], -diag);
    }
}

// ---------------- WMMA bf16 GEMM (64x64 tile) fused with exp row-sum ---------
#define LDT 80
__global__ __launch_bounds__(256) void k_gemm() {
    __shared__ __nv_bfloat16 Asm[64 * LDT];
    __shared__ __nv_bfloat16 Bsm[64 * LDT];
    __shared__ float         Csm[64 * 64];
    int bi = blockIdx.y * 64, bj = blockIdx.x * 64;
    int tid = threadIdx.x;

    // housekeeping: re-zero g_deg for the next run (first 586 blocks)
    int bid = blockIdx.y * 64 + blockIdx.x;
    if (bid < SCAN_BLKS) g_deg[bid * 256 + tid] = 0;

    #pragma unroll
    for (int pass = 0; pass < 2; pass++) {
        int row = pass * 32 + (tid >> 3);
        int col = (tid & 7) * 8;
        *(uint4*)(Asm + row * LDT + col) = *(const uint4*)(g_unb + (size_t)(bi + row) * EMB + col);
        *(uint4*)(Bsm + row * LDT + col) = *(const uint4*)(g_pnb + (size_t)(bj + row) * EMB + col);
    }
    __syncthreads();

    int wid = tid >> 5;
    int frow = wid >> 1;
    int fcol0 = (wid & 1) * 2;
    wmma::fragment<wmma::accumulator, 16, 16, 16, float> acc0, acc1;
    wmma::fill_fragment(acc0, 0.0f);
    wmma::fill_fragment(acc1, 0.0f);
    #pragma unroll
    for (int kk = 0; kk < 64; kk += 16) {
        wmma::fragment<wmma::matrix_a, 16, 16, 16, __nv_bfloat16, wmma::row_major> af;
        wmma::fragment<wmma::matrix_b, 16, 16, 16, __nv_bfloat16, wmma::col_major> bf0, bf1;
        wmma::load_matrix_sync(af, Asm + frow * 16 * LDT + kk, LDT);
        wmma::load_matrix_sync(bf0, Bsm + (fcol0 + 0) * 16 * LDT + kk, LDT);
        wmma::load_matrix_sync(bf1, Bsm + (fcol0 + 1) * 16 * LDT + kk, LDT);
        wmma::mma_sync(acc0, af, bf0, acc0);
        wmma::mma_sync(acc1, af, bf1, acc1);
    }
    wmma::store_matrix_sync(Csm + frow * 16 * 64 + (fcol0 + 0) * 16, acc0, 64, wmma::mem_row_major);
    wmma::store_matrix_sync(Csm + frow * 16 * 64 + (fcol0 + 1) * 16, acc1, 64, wmma::mem_row_major);
    __syncthreads();

    const float invTau = 1.0f / TAU;
    int row = tid >> 2;
    int seg = (tid & 3) * 16;
    const float* Crow = Csm + row * 64 + seg;
    float s = 0.0f;
    #pragma unroll
    for (int q = 0; q < 16; q++) s += __expf(Crow[q] * invTau);
    s += __shfl_xor_sync(0xffffffffu, s, 1);
    s += __shfl_xor_sync(0xffffffffu, s, 2);
    if ((tid & 3) == 0) atomicAdd(&g_rowsum[bi + row], s);
}

// ---------------- sum of log(rowsum); zero rowsum for next run ---------------
__global__ __launch_bounds__(256) void k_logsum() {
    int i = blockIdx.x * blockDim.x + threadIdx.x;
    float v = logf(g_rowsum[i]);
    g_rowsum[i] = 0.0f;
    #pragma unroll
    for (int o = 16; o; o >>= 1) v += __shfl_xor_sync(0xffffffffu, v, o);
    __shared__ float ws[8];
    int lane = threadIdx.x & 31, wid = threadIdx.x >> 5;
    if (lane == 0) ws[wid] = v;
    __syncthreads();
    if (threadIdx.x == 0) {
        float s = 0.f;
        #pragma unroll
        for (int k = 0; k < 8; k++) s += ws[k];
        atomicAdd(&g_scal[2], s);
    }
}

// ---------------- finalize; reset accumulators for next run ------------------
__global__ void k_final(float* out) {
    float bpr = g_scal[0] / BATCH;
    float reg = 0.5f * g_scal[1] / BATCH * REG_LAMBDA;
    float na  = g_scal[2] / BATCH * SSL_LAMBDA;
    out[0] = bpr + reg + na;
    g_scal[0] = 0.f; g_scal[1] = 0.f; g_scal[2] = 0.f; g_scal[3] = 0.f;
    g_ctr = 0;
}

// ---------------- host -------------------------------------------------------
extern "C" void kernel_launch(void* const* d_in, const int* in_sizes, int n_in,
                              void* d_out, int out_size) {
    const int*   user  = (const int*)d_in[0];
    const int*   pos   = (const int*)d_in[1];
    const int*   neg   = (const int*)d_in[2];
    const int*   arow  = (const int*)d_in[3];
    const int*   acol  = (const int*)d_in[4];
    const float* aval  = (const float*)d_in[5];
    const float* uw    = (const float*)d_in[6];
    const float* iw    = (const float*)d_in[7];
    float* out = (float*)d_out;

    __nv_bfloat16 *b0, *b1, *b2, *b3;
    cudaGetSymbolAddress((void**)&b0, g_b0);
    cudaGetSymbolAddress((void**)&b1, g_b1);
    cudaGetSymbolAddress((void**)&b2, g_b2);
    cudaGetSymbolAddress((void**)&b3, g_b3);

    const int TB = 256;
    const int edge_blocks = N_EDGES / TB;                  // 9375
    const int row_blocks  = (N_NODES * 32 + TB - 1) / TB;  // 18750

    k_combo<<<edge_blocks, TB>>>(uw, iw, arow);            // 1
    k_csr<<<SCAN_BLKS, TB>>>();                            // 2
    k_scatter<<<edge_blocks, TB>>>(arow, acol, aval);      // 3
    k_spmm<<<row_blocks, TB>>>(b0, b1);                    // 4
    k_spmm<<<row_blocks, TB>>>(b1, b2);                    // 5
    k_spmm<<<row_blocks, TB>>>(b2, b3);                    // 6
    k_gather<<<(BATCH * 32) / TB, TB>>>(user, pos, neg, uw, iw);   // 7
    k_gemm<<<dim3(BATCH / 64, BATCH / 64), TB>>>();        // 8
    k_logsum<<<BATCH / TB, TB>>>();                        // 9
    k_final<<<1, 1>>>(out);                                // 10
}